// round 8
// baseline (speedup 1.0000x reference)
#include <cuda_runtime.h>
#include <cuda_fp16.h>
#include <cstdint>
#include <math.h>

#define BATCH 64
#define ONUM  32
#define INUM  512
#define DD    64
#define OD    2048               // ONUM*DD

// ---------------- scratch (device globals) -----------------------------------
__device__ __half g_xhat[(size_t)BATCH * INUM * OD];   // [b][i][o][d] fp16, 134MB
__device__ float g_s[3][BATCH * OD];
__device__ float g_b1[(size_t)BATCH * INUM * ONUM];

// ---------------- helpers -----------------------------------------------------
__device__ __forceinline__ uint32_t smem_u32(const void* p) {
    uint32_t a;
    asm("{ .reg .u64 t; cvta.to.shared.u64 t, %1; cvt.u32.u64 %0, t; }" : "=r"(a) : "l"(p));
    return a;
}
__device__ __forceinline__ uint2 f4_to_h4(float4 v) {
    __half2 h0 = __floats2half2_rn(v.x, v.y);
    __half2 h1 = __floats2half2_rn(v.z, v.w);
    return make_uint2(*(uint32_t*)&h0, *(uint32_t*)&h1);
}
__device__ __forceinline__ uint32_t f2_to_h2(float a, float b) {
    __half2 h = __floats2half2_rn(a, b);
    return *(uint32_t*)&h;
}
__device__ __forceinline__ void ldmx4(uint32_t* r, uint32_t addr) {
    asm volatile("ldmatrix.sync.aligned.m8n8.x4.shared.b16 {%0,%1,%2,%3}, [%4];"
                 : "=r"(r[0]), "=r"(r[1]), "=r"(r[2]), "=r"(r[3]) : "r"(addr));
}
__device__ __forceinline__ void mma16816(float* c, const uint32_t* a, uint32_t b0, uint32_t b1) {
    asm volatile("mma.sync.aligned.m16n8k16.row.col.f32.f16.f16.f32 "
                 "{%0,%1,%2,%3}, {%4,%5,%6,%7}, {%8,%9}, {%0,%1,%2,%3};"
                 : "+f"(c[0]), "+f"(c[1]), "+f"(c[2]), "+f"(c[3])
                 : "r"(a[0]), "r"(a[1]), "r"(a[2]), "r"(a[3]), "r"(b0), "r"(b1));
}

// ---------------- zero --------------------------------------------------------
__global__ void zero_s_kernel() {
    int idx = blockIdx.x * blockDim.x + threadIdx.x;
    if (idx < 3 * BATCH * OD) (&g_s[0][0])[idx] = 0.0f;
}

// ---------------- HMMA GEMM: x_hat + fused s0 (at DRAM roofline) --------------
#define WT_S 72
#define XT_S 72
#define OT_S 136

__global__ __launch_bounds__(256, 2) void gemm_xhat_hmma(
    const float* __restrict__ x, const float* __restrict__ w)
{
    __shared__ __align__(16) __half Wt[128 * WT_S];  // [od][m]
    __shared__ __align__(16) __half Xt[64 * XT_S];   // [b][m]
    __shared__ __align__(16) __half Ot[64 * OT_S];   // [b][od 0..127]

    const int tid = threadIdx.x, wid = tid >> 5, lane = tid & 31;
    const int p = blockIdx.x;
    const int ibase = blockIdx.y * 16;

    const uint32_t wbase = smem_u32(Wt);
    const uint32_t xbase = smem_u32(Xt);

    const float4* wf4 = (const float4*)w;
    const float4* xf4 = (const float4*)x;

    const int wm = wid & 1;
    const int wn = wid >> 1;
    const int r0a = wm * 32;
    const int n0  = wn * 32;

    const int a_row_off = (lane & 7) + ((lane >> 3) & 1) * 8;
    const int a_col_off = (lane >= 16) ? 8 : 0;
    const int b_row_off = (lane & 7) + ((lane >> 4) & 1) * 8;
    const int b_col_off = ((lane >> 3) & 1) * 8;

    float s0acc[4][8];
#pragma unroll
    for (int j = 0; j < 4; j++)
#pragma unroll
        for (int e = 0; e < 8; e++) s0acc[j][e] = 0.0f;

    for (int t = 0; t < 16; t++) {
        const int i = ibase + t;

#pragma unroll
        for (int k = 0; k < 8; k++) {
            int g = tid + k * 256;
            int ol = g >> 10, rem = g & 1023;
            float4 v = wf4[(((size_t)(2 * p + ol) * INUM + i) << 10) + rem];
            *(uint2*)&Wt[(ol * 64 + (rem >> 4)) * WT_S + (rem & 15) * 4] = f4_to_h4(v);
        }
#pragma unroll
        for (int j = 0; j < 4; j++) {
            int idx = tid + j * 256;
            int b = idx >> 4, mq = idx & 15;
            float4 v = xf4[((size_t)b * INUM + i) * 16 + mq];
            *(uint2*)&Xt[b * XT_S + mq * 4] = f4_to_h4(v);
        }
        __syncthreads();

        float acc[2][4][4];
#pragma unroll
        for (int mt = 0; mt < 2; mt++)
#pragma unroll
            for (int nt = 0; nt < 4; nt++)
#pragma unroll
                for (int e = 0; e < 4; e++) acc[mt][nt][e] = 0.0f;

#pragma unroll
        for (int ks = 0; ks < 4; ks++) {
            const int kc = ks * 16;
            uint32_t afr[2][4], bfr[2][4];
#pragma unroll
            for (int mt = 0; mt < 2; mt++) {
                int row = r0a + mt * 16 + a_row_off;
                int col = kc + a_col_off;
                ldmx4(afr[mt], xbase + (row * XT_S + col) * 2);
            }
#pragma unroll
            for (int nt2 = 0; nt2 < 2; nt2++) {
                int row = n0 + nt2 * 16 + b_row_off;
                int col = kc + b_col_off;
                ldmx4(bfr[nt2], wbase + (row * WT_S + col) * 2);
            }
#pragma unroll
            for (int mt = 0; mt < 2; mt++) {
#pragma unroll
                for (int nt = 0; nt < 4; nt++) {
                    uint32_t b0 = bfr[nt >> 1][(nt & 1) * 2 + 0];
                    uint32_t b1 = bfr[nt >> 1][(nt & 1) * 2 + 1];
                    mma16816(acc[mt][nt], afr[mt], b0, b1);
                }
            }
        }

#pragma unroll
        for (int mt = 0; mt < 2; mt++) {
            int row = r0a + mt * 16 + (lane >> 2);
#pragma unroll
            for (int nt = 0; nt < 4; nt++) {
                int col = n0 + nt * 8 + (lane & 3) * 2;
                *(uint32_t*)&Ot[row * OT_S + col] = f2_to_h2(acc[mt][nt][0], acc[mt][nt][1]);
                *(uint32_t*)&Ot[(row + 8) * OT_S + col] = f2_to_h2(acc[mt][nt][2], acc[mt][nt][3]);
            }
        }
        __syncthreads();

#pragma unroll
        for (int j = 0; j < 4; j++) {
            int idx = tid + j * 256;
            int brow = idx >> 4, chunk = idx & 15;
            uint4 v = *(const uint4*)&Ot[brow * OT_S + chunk * 8];
            const __half2* h = (const __half2*)&v;
#pragma unroll
            for (int q = 0; q < 4; q++) {
                float2 f = __half22float2(h[q]);
                s0acc[j][q * 2 + 0] += f.x;
                s0acc[j][q * 2 + 1] += f.y;
            }
            *(uint4*)&g_xhat[((size_t)brow * INUM + i) * OD + p * 128 + chunk * 8] = v;
        }
        __syncthreads();
    }

    const float sc = 1.0f / (float)ONUM;
#pragma unroll
    for (int j = 0; j < 4; j++) {
        int idx = tid + j * 256;
        int brow = idx >> 4, chunk = idx & 15;
        float* sp = &g_s[0][brow * OD + p * 128 + chunk * 8];
#pragma unroll
        for (int e = 0; e < 8; e++)
            atomicAdd(sp + e, s0acc[j][e] * sc);
    }
}

// ---------------- final squash ------------------------------------------------
__global__ void squash_kernel(const float* __restrict__ s, float* __restrict__ v)
{
    int gw   = (blockIdx.x * blockDim.x + threadIdx.x) >> 5;
    int lane = threadIdx.x & 31;
    if (gw >= BATCH * ONUM) return;
    const float* row = s + (size_t)gw * 64;
    float a = row[lane];
    float b = row[lane + 32];
    float ss = a * a + b * b;
#pragma unroll
    for (int off = 16; off; off >>= 1) ss += __shfl_xor_sync(0xffffffffu, ss, off);
    float n = sqrtf(ss);
    float f = (ss / (1.0f + ss)) / (n + 1e-8f);
    v[(size_t)gw * 64 + lane]      = a * f;
    v[(size_t)gw * 64 + lane + 32] = b * f;
}

// ---------------- routing pass v6 ---------------------------------------------
// Round-4 structure (best measured): grid (64,4), block 128, 32 i/warp,
// lane = o, LDG depth-2 prefetch, register opv/sacc.
// Changes: inline squash prologue, 4-way split dot, max-free softmax,
// b1 prefetch (MODE 1).
#define OPS_S 68
#define RED_S 65
template <int MODE>
__global__ __launch_bounds__(128) void route_v6(
    const float* __restrict__ s_prev, float* __restrict__ s_next)
{
    __shared__ __align__(16) float ops[ONUM * OPS_S];
    __shared__ float red[ONUM * RED_S];

    const int tid = threadIdx.x, wid = tid >> 5, lane = tid & 31;
    const int b = blockIdx.x;
    const int i0 = (blockIdx.y * 4 + wid) * 32;

    // start the x_hat stream before anything else
    const uint4* xp = (const uint4*)(g_xhat + (size_t)b * INUM * OD + (size_t)i0 * OD + lane * 64);
    uint4 cur[8], nxt[8];
#pragma unroll
    for (int c = 0; c < 8; c++) cur[c] = xp[c];
#pragma unroll
    for (int c = 0; c < 8; c++) nxt[c] = xp[(OD / 8) + c];

    // inline squash: ops[o][:] = squash(s_prev[b])[o][:]; each warp does 8 rows
#pragma unroll
    for (int r = 0; r < 8; r++) {
        int row = wid * 8 + r;
        float a = s_prev[(size_t)b * OD + row * 64 + lane];
        float c2 = s_prev[(size_t)b * OD + row * 64 + lane + 32];
        float ss = a * a + c2 * c2;
#pragma unroll
        for (int off = 16; off; off >>= 1) ss += __shfl_xor_sync(0xffffffffu, ss, off);
        float n = sqrtf(ss);
        float f = (ss / (1.0f + ss)) / (n + 1e-8f);
        ops[row * OPS_S + lane]      = a * f;
        ops[row * OPS_S + lane + 32] = c2 * f;
    }
    for (int k = tid; k < ONUM * RED_S; k += 128) red[k] = 0.0f;
    __syncthreads();

    // out_prev[o=lane][:] into registers
    float opv[64];
#pragma unroll
    for (int c = 0; c < 16; c++) {
        float4 v = *(const float4*)&ops[lane * OPS_S + c * 4];
        opv[c * 4 + 0] = v.x; opv[c * 4 + 1] = v.y;
        opv[c * 4 + 2] = v.z; opv[c * 4 + 3] = v.w;
    }

    float sacc[64];
#pragma unroll
    for (int d = 0; d < 64; d++) sacc[d] = 0.0f;

    float* b1p = g_b1 + ((size_t)b * INUM + i0) * ONUM + lane;
    float b1v = (MODE == 1) ? b1p[0] : 0.0f;

    for (int ii = 0; ii < 32; ii++) {
        if (ii + 1 < 32) {
            const uint4* np = xp + (size_t)(ii + 1) * (OD / 8);
            if (ii + 2 < 32) {
                // rotate: cur <- nxt happens below; prefetch ii+2 into nxt after use
            }
        }

        // 4-way split agreement dot (chain depth 16 instead of 64)
        float pd0 = 0.0f, pd1 = 0.0f, pd2 = 0.0f, pd3 = 0.0f;
#pragma unroll
        for (int c = 0; c < 8; c += 4) {
            const __half2* h0 = (const __half2*)&cur[c];
            const __half2* h1 = (const __half2*)&cur[c + 1];
            const __half2* h2 = (const __half2*)&cur[c + 2];
            const __half2* h3 = (const __half2*)&cur[c + 3];
#pragma unroll
            for (int q = 0; q < 4; q++) {
                float2 a0 = __half22float2(h0[q]);
                float2 a1 = __half22float2(h1[q]);
                float2 a2 = __half22float2(h2[q]);
                float2 a3 = __half22float2(h3[q]);
                pd0 = fmaf(a0.x, opv[(c + 0) * 8 + q * 2], fmaf(a0.y, opv[(c + 0) * 8 + q * 2 + 1], pd0));
                pd1 = fmaf(a1.x, opv[(c + 1) * 8 + q * 2], fmaf(a1.y, opv[(c + 1) * 8 + q * 2 + 1], pd1));
                pd2 = fmaf(a2.x, opv[(c + 2) * 8 + q * 2], fmaf(a2.y, opv[(c + 2) * 8 + q * 2 + 1], pd2));
                pd3 = fmaf(a3.x, opv[(c + 3) * 8 + q * 2], fmaf(a3.y, opv[(c + 3) * 8 + q * 2 + 1], pd3));
            }
        }
        float pdot = (pd0 + pd1) + (pd2 + pd3);

        if (MODE == 1) {
            pdot += b1v;
            if (ii + 1 < 32) b1v = b1p[(ii + 1) * ONUM];   // prefetch next (off critical path)
        } else {
            b1p[ii * ONUM] = pdot;
        }

        // max-free softmax over 32 o's (5 shuffles instead of 10)
        float e = __expf(pdot);
        float ssum = e;
#pragma unroll
        for (int off = 16; off; off >>= 1)
            ssum += __shfl_xor_sync(0xffffffffu, ssum, off);
        float c = e / ssum;

        // weighted accumulate (independent of next dot; overlaps)
#pragma unroll
        for (int cc = 0; cc < 8; cc++) {
            const __half2* h = (const __half2*)&cur[cc];
            float2 f0 = __half22float2(h[0]);
            float2 f1 = __half22float2(h[1]);
            float2 f2 = __half22float2(h[2]);
            float2 f3 = __half22float2(h[3]);
            sacc[cc * 8 + 0] += c * f0.x; sacc[cc * 8 + 1] += c * f0.y;
            sacc[cc * 8 + 2] += c * f1.x; sacc[cc * 8 + 3] += c * f1.y;
            sacc[cc * 8 + 4] += c * f2.x; sacc[cc * 8 + 5] += c * f2.y;
            sacc[cc * 8 + 6] += c * f3.x; sacc[cc * 8 + 7] += c * f3.y;
        }

        // rotate prefetch buffers and issue ii+2
#pragma unroll
        for (int c2 = 0; c2 < 8; c2++) cur[c2] = nxt[c2];
        if (ii + 2 < 32) {
            const uint4* np = xp + (size_t)(ii + 2) * (OD / 8);
#pragma unroll
            for (int c2 = 0; c2 < 8; c2++) nxt[c2] = np[c2];
        }
    }

    // CTA reduction (stride-65: bank = (o+d) mod 32, conflict-free)
#pragma unroll
    for (int d = 0; d < 64; d++)
        atomicAdd(&red[lane * RED_S + d], sacc[d]);
    __syncthreads();

    for (int k = tid; k < OD; k += 128) {
        int o = k >> 6, d = k & 63;
        atomicAdd(&s_next[(size_t)b * OD + k], red[o * RED_S + d]);
    }
}

// ---------------- launch ------------------------------------------------------
extern "C" void kernel_launch(void* const* d_in, const int* in_sizes, int n_in,
                              void* d_out, int out_size)
{
    const float* x = (const float*)d_in[0];
    const float* w = (const float*)d_in[1];
    float* out = (float*)d_out;

    float* s_base;  cudaGetSymbolAddress((void**)&s_base,  g_s);
    float* s0 = s_base;
    float* s1 = s_base + BATCH * OD;
    float* s2 = s_base + 2 * BATCH * OD;

    zero_s_kernel<<<(3 * BATCH * OD + 255) / 256, 256>>>();

    gemm_xhat_hmma<<<dim3(16, 32), 256>>>(x, w);

    route_v6<0><<<dim3(BATCH, 4), 128>>>(s0, s1);

    route_v6<1><<<dim3(BATCH, 4), 128>>>(s1, s2);

    squash_kernel<<<(BATCH * ONUM) / 8, 256>>>(s2, out);
}

// round 9
// speedup vs baseline: 1.1743x; 1.1743x over previous
#include <cuda_runtime.h>
#include <cuda_fp16.h>
#include <cstdint>
#include <math.h>

#define BATCH 64
#define ONUM  32
#define INUM  512
#define DD    64
#define OD    2048               // ONUM*DD

// ---------------- scratch (device globals) -----------------------------------
__device__ __half g_xhat[(size_t)BATCH * INUM * OD];   // [b][i][o][d] fp16, 134MB
__device__ float g_s[3][BATCH * OD];
__device__ float g_out0[BATCH * OD];
__device__ float g_out1[BATCH * OD];
__device__ float g_b1[(size_t)BATCH * INUM * ONUM];

// ---------------- helpers -----------------------------------------------------
__device__ __forceinline__ uint32_t smem_u32(const void* p) {
    uint32_t a;
    asm("{ .reg .u64 t; cvta.to.shared.u64 t, %1; cvt.u32.u64 %0, t; }" : "=r"(a) : "l"(p));
    return a;
}
__device__ __forceinline__ uint2 f4_to_h4(float4 v) {
    __half2 h0 = __floats2half2_rn(v.x, v.y);
    __half2 h1 = __floats2half2_rn(v.z, v.w);
    return make_uint2(*(uint32_t*)&h0, *(uint32_t*)&h1);
}
__device__ __forceinline__ uint32_t f2_to_h2(float a, float b) {
    __half2 h = __floats2half2_rn(a, b);
    return *(uint32_t*)&h;
}
__device__ __forceinline__ void ldmx4(uint32_t* r, uint32_t addr) {
    asm volatile("ldmatrix.sync.aligned.m8n8.x4.shared.b16 {%0,%1,%2,%3}, [%4];"
                 : "=r"(r[0]), "=r"(r[1]), "=r"(r[2]), "=r"(r[3]) : "r"(addr));
}
__device__ __forceinline__ void mma16816(float* c, const uint32_t* a, uint32_t b0, uint32_t b1) {
    asm volatile("mma.sync.aligned.m16n8k16.row.col.f32.f16.f16.f32 "
                 "{%0,%1,%2,%3}, {%4,%5,%6,%7}, {%8,%9}, {%0,%1,%2,%3};"
                 : "+f"(c[0]), "+f"(c[1]), "+f"(c[2]), "+f"(c[3])
                 : "r"(a[0]), "r"(a[1]), "r"(a[2]), "r"(a[3]), "r"(b0), "r"(b1));
}

// ---------------- zero --------------------------------------------------------
__global__ void zero_s_kernel() {
    int idx = blockIdx.x * blockDim.x + threadIdx.x;
    if (idx < 3 * BATCH * OD) (&g_s[0][0])[idx] = 0.0f;
}

// ---------------- HMMA GEMM: x_hat + fused s0 (at DRAM roofline) --------------
#define WT_S 72
#define XT_S 72
#define OT_S 136

__global__ __launch_bounds__(256, 2) void gemm_xhat_hmma(
    const float* __restrict__ x, const float* __restrict__ w)
{
    __shared__ __align__(16) __half Wt[128 * WT_S];  // [od][m]
    __shared__ __align__(16) __half Xt[64 * XT_S];   // [b][m]
    __shared__ __align__(16) __half Ot[64 * OT_S];   // [b][od 0..127]

    const int tid = threadIdx.x, wid = tid >> 5, lane = tid & 31;
    const int p = blockIdx.x;
    const int ibase = blockIdx.y * 16;

    const uint32_t wbase = smem_u32(Wt);
    const uint32_t xbase = smem_u32(Xt);

    const float4* wf4 = (const float4*)w;
    const float4* xf4 = (const float4*)x;

    const int wm = wid & 1;
    const int wn = wid >> 1;
    const int r0a = wm * 32;
    const int n0  = wn * 32;

    const int a_row_off = (lane & 7) + ((lane >> 3) & 1) * 8;
    const int a_col_off = (lane >= 16) ? 8 : 0;
    const int b_row_off = (lane & 7) + ((lane >> 4) & 1) * 8;
    const int b_col_off = ((lane >> 3) & 1) * 8;

    float s0acc[4][8];
#pragma unroll
    for (int j = 0; j < 4; j++)
#pragma unroll
        for (int e = 0; e < 8; e++) s0acc[j][e] = 0.0f;

    for (int t = 0; t < 16; t++) {
        const int i = ibase + t;

#pragma unroll
        for (int k = 0; k < 8; k++) {
            int g = tid + k * 256;
            int ol = g >> 10, rem = g & 1023;
            float4 v = wf4[(((size_t)(2 * p + ol) * INUM + i) << 10) + rem];
            *(uint2*)&Wt[(ol * 64 + (rem >> 4)) * WT_S + (rem & 15) * 4] = f4_to_h4(v);
        }
#pragma unroll
        for (int j = 0; j < 4; j++) {
            int idx = tid + j * 256;
            int b = idx >> 4, mq = idx & 15;
            float4 v = xf4[((size_t)b * INUM + i) * 16 + mq];
            *(uint2*)&Xt[b * XT_S + mq * 4] = f4_to_h4(v);
        }
        __syncthreads();

        float acc[2][4][4];
#pragma unroll
        for (int mt = 0; mt < 2; mt++)
#pragma unroll
            for (int nt = 0; nt < 4; nt++)
#pragma unroll
                for (int e = 0; e < 4; e++) acc[mt][nt][e] = 0.0f;

#pragma unroll
        for (int ks = 0; ks < 4; ks++) {
            const int kc = ks * 16;
            uint32_t afr[2][4], bfr[2][4];
#pragma unroll
            for (int mt = 0; mt < 2; mt++) {
                int row = r0a + mt * 16 + a_row_off;
                int col = kc + a_col_off;
                ldmx4(afr[mt], xbase + (row * XT_S + col) * 2);
            }
#pragma unroll
            for (int nt2 = 0; nt2 < 2; nt2++) {
                int row = n0 + nt2 * 16 + b_row_off;
                int col = kc + b_col_off;
                ldmx4(bfr[nt2], wbase + (row * WT_S + col) * 2);
            }
#pragma unroll
            for (int mt = 0; mt < 2; mt++) {
#pragma unroll
                for (int nt = 0; nt < 4; nt++) {
                    uint32_t b0 = bfr[nt >> 1][(nt & 1) * 2 + 0];
                    uint32_t b1 = bfr[nt >> 1][(nt & 1) * 2 + 1];
                    mma16816(acc[mt][nt], afr[mt], b0, b1);
                }
            }
        }

#pragma unroll
        for (int mt = 0; mt < 2; mt++) {
            int row = r0a + mt * 16 + (lane >> 2);
#pragma unroll
            for (int nt = 0; nt < 4; nt++) {
                int col = n0 + nt * 8 + (lane & 3) * 2;
                *(uint32_t*)&Ot[row * OT_S + col] = f2_to_h2(acc[mt][nt][0], acc[mt][nt][1]);
                *(uint32_t*)&Ot[(row + 8) * OT_S + col] = f2_to_h2(acc[mt][nt][2], acc[mt][nt][3]);
            }
        }
        __syncthreads();

#pragma unroll
        for (int j = 0; j < 4; j++) {
            int idx = tid + j * 256;
            int brow = idx >> 4, chunk = idx & 15;
            uint4 v = *(const uint4*)&Ot[brow * OT_S + chunk * 8];
            const __half2* h = (const __half2*)&v;
#pragma unroll
            for (int q = 0; q < 4; q++) {
                float2 f = __half22float2(h[q]);
                s0acc[j][q * 2 + 0] += f.x;
                s0acc[j][q * 2 + 1] += f.y;
            }
            *(uint4*)&g_xhat[((size_t)brow * INUM + i) * OD + p * 128 + chunk * 8] = v;
        }
        __syncthreads();
    }

    const float sc = 1.0f / (float)ONUM;
#pragma unroll
    for (int j = 0; j < 4; j++) {
        int idx = tid + j * 256;
        int brow = idx >> 4, chunk = idx & 15;
        float* sp = &g_s[0][brow * OD + p * 128 + chunk * 8];
#pragma unroll
        for (int e = 0; e < 8; e++)
            atomicAdd(sp + e, s0acc[j][e] * sc);
    }
}

// ---------------- squash ------------------------------------------------------
__global__ void squash_kernel(const float* __restrict__ s, float* __restrict__ v)
{
    int gw   = (blockIdx.x * blockDim.x + threadIdx.x) >> 5;
    int lane = threadIdx.x & 31;
    if (gw >= BATCH * ONUM) return;
    const float* row = s + (size_t)gw * 64;
    float a = row[lane];
    float b = row[lane + 32];
    float ss = a * a + b * b;
#pragma unroll
    for (int off = 16; off; off >>= 1) ss += __shfl_xor_sync(0xffffffffu, ss, off);
    float n = sqrtf(ss);
    float f = (ss / (1.0f + ss)) / (n + 1e-8f);
    v[(size_t)gw * 64 + lane]      = a * f;
    v[(size_t)gw * 64 + lane + 32] = b * f;
}

// ---------------- routing pass (round-4 structure + serial-path cuts) ---------
// grid (64, 4), block 128 (4 warps). warp -> (b, 32 i's); lane = o.
template <int MODE>
__global__ __launch_bounds__(128) void route_v7(
    const float* __restrict__ out_prev, float* __restrict__ s_next)
{
    __shared__ float red[ONUM * 65];

    const int tid = threadIdx.x, wid = tid >> 5, lane = tid & 31;
    const int b = blockIdx.x;
    const int i0 = (blockIdx.y * 4 + wid) * 32;

    for (int k = tid; k < ONUM * 65; k += 128) red[k] = 0.0f;

    float opv[64];
    {
        const float4* opf = (const float4*)(out_prev + (size_t)b * OD + lane * 64);
#pragma unroll
        for (int c = 0; c < 16; c++) {
            float4 v = opf[c];
            opv[c * 4 + 0] = v.x; opv[c * 4 + 1] = v.y;
            opv[c * 4 + 2] = v.z; opv[c * 4 + 3] = v.w;
        }
    }
    __syncthreads();

    float sacc[64];
#pragma unroll
    for (int d = 0; d < 64; d++) sacc[d] = 0.0f;

    const uint4* xp = (const uint4*)(g_xhat + (size_t)b * INUM * OD + (size_t)i0 * OD + lane * 64);
    float* b1p = g_b1 + ((size_t)b * INUM + i0) * ONUM + lane;
    float b1v = (MODE == 1) ? b1p[0] : 0.0f;

    uint4 cur[8], nxt[8];
#pragma unroll
    for (int c = 0; c < 8; c++) cur[c] = xp[c];

    for (int ii = 0; ii < 32; ii++) {
        if (ii + 1 < 32) {
            const uint4* np = xp + (size_t)(ii + 1) * (OD / 8);
#pragma unroll
            for (int c = 0; c < 8; c++) nxt[c] = np[c];
        }

        // 2-way split agreement dot (halved dependency chain)
        float pd0 = 0.0f, pd1 = 0.0f;
#pragma unroll
        for (int c = 0; c < 8; c += 2) {
            const __half2* h0 = (const __half2*)&cur[c];
            const __half2* h1 = (const __half2*)&cur[c + 1];
#pragma unroll
            for (int q = 0; q < 4; q++) {
                float2 a0 = __half22float2(h0[q]);
                float2 a1 = __half22float2(h1[q]);
                pd0 = fmaf(a0.x, opv[c * 8 + q * 2],       fmaf(a0.y, opv[c * 8 + q * 2 + 1],       pd0));
                pd1 = fmaf(a1.x, opv[(c + 1) * 8 + q * 2], fmaf(a1.y, opv[(c + 1) * 8 + q * 2 + 1], pd1));
            }
        }
        float pdot = pd0 + pd1;

        if (MODE == 1) {
            pdot += b1v;
            if (ii + 1 < 32) b1v = b1p[(ii + 1) * ONUM];   // prefetch off critical path
        } else {
            b1p[ii * ONUM] = pdot;
        }

        // max-free softmax over 32 o's (logits bounded; mathematically identical)
        float e = __expf(pdot);
        float ssum = e;
#pragma unroll
        for (int off = 16; off; off >>= 1)
            ssum += __shfl_xor_sync(0xffffffffu, ssum, off);
        float c = e / ssum;

#pragma unroll
        for (int cc = 0; cc < 8; cc++) {
            const __half2* h = (const __half2*)&cur[cc];
            float2 f0 = __half22float2(h[0]);
            float2 f1 = __half22float2(h[1]);
            float2 f2 = __half22float2(h[2]);
            float2 f3 = __half22float2(h[3]);
            sacc[cc * 8 + 0] += c * f0.x; sacc[cc * 8 + 1] += c * f0.y;
            sacc[cc * 8 + 2] += c * f1.x; sacc[cc * 8 + 3] += c * f1.y;
            sacc[cc * 8 + 4] += c * f2.x; sacc[cc * 8 + 5] += c * f2.y;
            sacc[cc * 8 + 6] += c * f3.x; sacc[cc * 8 + 7] += c * f3.y;
        }
#pragma unroll
        for (int c2 = 0; c2 < 8; c2++) cur[c2] = nxt[c2];
    }

#pragma unroll
    for (int d = 0; d < 64; d++)
        atomicAdd(&red[lane * 65 + d], sacc[d]);
    __syncthreads();

    for (int k = tid; k < OD; k += 128) {
        int o = k >> 6, d = k & 63;
        atomicAdd(&s_next[(size_t)b * OD + k], red[o * 65 + d]);
    }
}

// ---------------- launch ------------------------------------------------------
extern "C" void kernel_launch(void* const* d_in, const int* in_sizes, int n_in,
                              void* d_out, int out_size)
{
    const float* x = (const float*)d_in[0];
    const float* w = (const float*)d_in[1];
    float* out = (float*)d_out;

    float* s_base;  cudaGetSymbolAddress((void**)&s_base,  g_s);
    float* out0;    cudaGetSymbolAddress((void**)&out0,    g_out0);
    float* out1;    cudaGetSymbolAddress((void**)&out1,    g_out1);
    float* s0 = s_base;
    float* s1 = s_base + BATCH * OD;
    float* s2 = s_base + 2 * BATCH * OD;

    zero_s_kernel<<<(3 * BATCH * OD + 255) / 256, 256>>>();

    gemm_xhat_hmma<<<dim3(16, 32), 256>>>(x, w);

    squash_kernel<<<(BATCH * ONUM) / 8, 256>>>(s0, out0);

    route_v7<0><<<dim3(BATCH, 4), 128>>>(out0, s1);

    squash_kernel<<<(BATCH * ONUM) / 8, 256>>>(s1, out1);

    route_v7<1><<<dim3(BATCH, 4), 128>>>(out1, s2);

    squash_kernel<<<(BATCH * ONUM) / 8, 256>>>(s2, out);
}